// round 15
// baseline (speedup 1.0000x reference)
#include <cuda_runtime.h>
#include <math.h>

#define B_ 4
#define C_ 128
#define T_ 32
#define H_ 24
#define W_ 24
#define M_ 3
#define HW_ (H_*W_)               // 576
#define NPER (B_*C_*T_*HW_)       // 9437184 elements per output tensor

// Scratch (device globals; no allocation allowed)
__device__ float g_qg[B_*T_*C_];     // [b][t][c]  pooled q
__device__ float g_alpha[B_*M_*T_];  // [b][m][t]  softmax mixture weights

// ---------------------------------------------------------------------------
// Kernel 1: spatial mean pool of q. One WARP per (b,c,t) slice. (measured 9.6us)
// ---------------------------------------------------------------------------
__global__ __launch_bounds__(256) void pool_kernel(const float4* __restrict__ q4) {
    int w = threadIdx.x >> 5, lane = threadIdx.x & 31;
    int idx = blockIdx.x * 8 + w;          // b*C*T + c*T + t
    const float4* p = q4 + (size_t)idx * 144;
    float4 a = p[lane], b4 = p[lane + 32], c4 = p[lane + 64], d4 = p[lane + 96];
    float s = a.x + a.y + a.z + a.w + b4.x + b4.y + b4.z + b4.w
            + c4.x + c4.y + c4.z + c4.w + d4.x + d4.y + d4.z + d4.w;
    if (lane < 16) {
        float4 e = p[lane + 128];
        s += e.x + e.y + e.z + e.w;
    }
    #pragma unroll
    for (int o = 16; o; o >>= 1) s += __shfl_down_sync(0xffffffffu, s, o);
    if (lane == 0) {
        int t = idx % T_, c = (idx / T_) % C_, b = idx / (T_ * C_);
        g_qg[(b * T_ + t) * C_ + c] = s * (1.0f / HW_);
    }
}

// ---------------------------------------------------------------------------
// Kernel 2 (measured ~5us): grid (B, 4). Each block owns 8 output timesteps,
// recomputes 2-timestep causal halo locally.
// ---------------------------------------------------------------------------
__global__ __launch_bounds__(256) void mix_kernel(const float* __restrict__ pre_w,
                                                  const float* __restrict__ pre_b,
                                                  const float* __restrict__ mix_w,
                                                  const float* __restrict__ mix_b) {
    int b = blockIdx.x, tg = blockIdx.y, tid = threadIdx.x;
    const int T0 = tg * 8;
    __shared__ float sq[10 * C_];
    __shared__ float sh[10 * C_];
    __shared__ float wsm[M_ * 3 * C_];
    __shared__ float lg[M_ * 8];

    for (int i = tid; i < 10 * (C_ / 4); i += 256) {
        int row = i / (C_ / 4), c4i = i % (C_ / 4);
        int tt = T0 - 2 + row;
        float4 val = make_float4(0.f, 0.f, 0.f, 0.f);
        if (tt >= 0) val = ((const float4*)(g_qg + (b * T_ + tt) * C_))[c4i];
        ((float4*)sq)[i] = val;
    }
    for (int i = tid; i < M_ * C_ * 3; i += 256) {
        int m = i / (C_ * 3), r = i % (C_ * 3);
        int cc = r / 3, j = r % 3;
        wsm[(m * 3 + j) * C_ + cc] = mix_w[i];
    }
    __syncthreads();

    int o = tid & 127, grp = tid >> 7;
    float acc[10];
    #pragma unroll
    for (int i = 0; i < 10; ++i) acc[i] = 0.f;

    const float4* wrow = (const float4*)(pre_w + o * C_) + grp * 16;
    #pragma unroll 4
    for (int c4 = 0; c4 < 16; ++c4) {
        float4 wv = wrow[c4];
        int cbase = grp * 64 + c4 * 4;
        #pragma unroll
        for (int i = 0; i < 10; ++i) {
            float4 sv = *(const float4*)&sq[i * C_ + cbase];
            acc[i] = fmaf(wv.x, sv.x,
                     fmaf(wv.y, sv.y,
                     fmaf(wv.z, sv.z,
                     fmaf(wv.w, sv.w, acc[i]))));
        }
    }
    __syncthreads();
    if (grp == 1) {
        #pragma unroll
        for (int i = 0; i < 10; ++i) sq[i * C_ + o] = acc[i];
    }
    __syncthreads();
    if (grp == 0) {
        float pb = pre_b[o];
        #pragma unroll
        for (int i = 0; i < 10; ++i) {
            float x = acc[i] + sq[i * C_ + o] + pb;
            sh[i * C_ + o] = 0.5f * x * (1.0f + erff(x * 0.70710678118654752440f));
        }
    }
    __syncthreads();

    if (tid < 24) {
        int m = tid / 8, tl = tid % 8;
        float a0 = mix_b[m], a1 = 0.f, a2 = 0.f, a3 = 0.f;
        #pragma unroll
        for (int j = 0; j < 3; ++j) {
            int tt = T0 + tl - 2 + j;
            if (tt >= 0) {
                const float* hp = sh + (tl + j) * C_;
                const float* wp = wsm + (m * 3 + j) * C_;
                #pragma unroll 4
                for (int c = 0; c < C_; c += 4) {
                    a0 = fmaf(wp[c],     hp[c],     a0);
                    a1 = fmaf(wp[c + 1], hp[c + 1], a1);
                    a2 = fmaf(wp[c + 2], hp[c + 2], a2);
                    a3 = fmaf(wp[c + 3], hp[c + 3], a3);
                }
            }
        }
        lg[m * 8 + tl] = (a0 + a1) + (a2 + a3);
    }
    __syncthreads();
    if (tid < 8) {
        int t = T0 + tid;
        float l0 = lg[tid], l1 = lg[8 + tid], l2 = lg[16 + tid];
        float mx = fmaxf(l0, fmaxf(l1, l2));
        float e0 = expf(l0 - mx), e1 = expf(l1 - mx), e2 = expf(l2 - mx);
        float inv = 1.f / (e0 + e1 + e2);
        g_alpha[(b * M_ + 0) * T_ + t] = e0 * inv;
        g_alpha[(b * M_ + 1) * T_ + t] = e1 * inv;
        g_alpha[(b * M_ + 2) * T_ + t] = e2 * inv;
    }
}

// ---------------------------------------------------------------------------
// Kernel 3: mixture depthwise causal 3D conv, ONE tensor (k or v) per block
// (blockIdx.z = b*2 + tensor), TWO channels per block (2 x 36 threads).
// Per-thread tile: 2 rows x 8 cols x 2 timesteps. A 12-float row read
// (3 LDS.128) feeds 8 outputs; weight quads halve (one tensor).
// Register prefetch double-buffer + hoisted W taps kept from R14.
// ---------------------------------------------------------------------------
#define TT    8
#define RS    28       // padded row stride (floats)
#define SLICE (26*RS)  // 728 floats per padded slice
#define WF2   72       // 2 to * 9 (d,dh) * 4 (dw padded), one tensor

__global__ __launch_bounds__(72) void conv_kernel(
    const float* __restrict__ kin, const float* __restrict__ vin,
    const float* __restrict__ Wk,  const float* __restrict__ Wv,
    float* __restrict__ out) {
    __shared__ float sm[8 * SLICE + 2 * WF2 + 32];  // [ch][4 slices] + wf + alphas
    float* wfall = sm + 8 * SLICE;
    float* asm_  = wfall + 2 * WF2;                 // alphas [m][8]

    int t0 = blockIdx.x * TT;
    int z = blockIdx.z;              // b*2 + tsel
    int b = z >> 1, tsel = z & 1;
    int tid = threadIdx.x;
    int ch = tid / 36, lt = tid % 36;
    int c = blockIdx.y * 2 + ch;
    float* base = sm + ch * 4 * SLICE;
    float* wf = wfall + ch * WF2;

    int hi = lt / 3, seg = lt % 3;
    int h0 = hi * 2, w0 = seg * 8;
    int lrow = lt / 3, lcol = (lt % 3) * 8;   // loader: rows lrow & lrow+12

    size_t bc = (size_t)b * C_ + c;
    const float* xbase = (tsel ? vin : kin) + bc * T_ * HW_;
    float* obase = out + (size_t)tsel * NPER + bc * T_ * HW_;
    const float* Wc = (tsel ? Wv : Wk) + c * 27;

    // hoist W taps for this thread's two wf slots (idx = lt, lt+36)
    float wA0 = 0.f, wA1 = 0.f, wA2 = 0.f, wB0 = 0.f, wB1 = 0.f, wB2 = 0.f;
    int toA, toB;
    {
        int idx = lt;
        int dw = idx & 3, g = idx >> 2;       // g = to*9 + qd
        toA = g / 9;
        int qd = g % 9;
        int j = (qd / 3) * 9 + (qd % 3) * 3 + dw;
        if (dw < 3) { wA0 = Wc[j]; wA1 = Wc[C_ * 27 + j]; wA2 = Wc[2 * C_ * 27 + j]; }
        idx = lt + 36;
        dw = idx & 3; g = idx >> 2;
        toB = g / 9;
        qd = g % 9;
        j = (qd / 3) * 9 + (qd % 3) * 3 + dw;
        if (dw < 3) { wB0 = Wc[j]; wB1 = Wc[C_ * 27 + j]; wB2 = Wc[2 * C_ * 27 + j]; }
    }

    // zero all slices (borders + temporal zero padding)
    for (int i = tid; i < (8 * SLICE) / 4; i += 72)
        ((float4*)sm)[i] = make_float4(0.f, 0.f, 0.f, 0.f);
    // stage alphas for this block's 8 timesteps (shared by both channels)
    if (tid < 24) {
        int m = tid / 8, tl = tid % 8;
        asm_[m * 8 + tl] = g_alpha[(b * M_ + m) * T_ + t0 + tl];
    }
    __syncthreads();   // zeros + alphas visible

    // halo slices t0-2, t0-1
    #pragma unroll
    for (int s = 0; s < 2; ++s) {
        int tt = t0 - 2 + s;
        if (tt >= 0) {
            int slot = tt & 3;
            const float* gx = xbase + (size_t)tt * HW_ + lt * 8;
            float4 a0 = ((const float4*)gx)[0], a1 = ((const float4*)gx)[1];
            float4 b0 = ((const float4*)(gx + 288))[0], b1 = ((const float4*)(gx + 288))[1];
            float* d0 = base + slot * SLICE + (lrow + 1) * RS + lcol + 1;
            float* d1 = base + slot * SLICE + (lrow + 13) * RS + lcol + 1;
            d0[0]=a0.x; d0[1]=a0.y; d0[2]=a0.z; d0[3]=a0.w;
            d0[4]=a1.x; d0[5]=a1.y; d0[6]=a1.z; d0[7]=a1.w;
            d1[0]=b0.x; d1[1]=b0.y; d1[2]=b0.z; d1[3]=b0.w;
            d1[4]=b1.x; d1[5]=b1.y; d1[6]=b1.z; d1[7]=b1.w;
        }
    }

    // prefetch first body pair (t0, t0+1): per slice 4 float4 (2 row-chunks)
    float4 pf[2][4];
    #pragma unroll
    for (int s = 0; s < 2; ++s) {
        const float* gx = xbase + (size_t)(t0 + s) * HW_ + lt * 8;
        pf[s][0] = ((const float4*)gx)[0]; pf[s][1] = ((const float4*)gx)[1];
        pf[s][2] = ((const float4*)(gx + 288))[0]; pf[s][3] = ((const float4*)(gx + 288))[1];
    }

    #pragma unroll 1
    for (int p = 0; p < TT / 2; ++p) {
        int t = t0 + 2 * p;
        __syncthreads();   // previous iter's reads done before slot overwrite
        #pragma unroll
        for (int s = 0; s < 2; ++s) {
            int slot = (t + s) & 3;
            float* d0 = base + slot * SLICE + (lrow + 1) * RS + lcol + 1;
            float* d1 = base + slot * SLICE + (lrow + 13) * RS + lcol + 1;
            d0[0]=pf[s][0].x; d0[1]=pf[s][0].y; d0[2]=pf[s][0].z; d0[3]=pf[s][0].w;
            d0[4]=pf[s][1].x; d0[5]=pf[s][1].y; d0[6]=pf[s][1].z; d0[7]=pf[s][1].w;
            d1[0]=pf[s][2].x; d1[1]=pf[s][2].y; d1[2]=pf[s][2].z; d1[3]=pf[s][2].w;
            d1[4]=pf[s][3].x; d1[5]=pf[s][3].y; d1[6]=pf[s][3].z; d1[7]=pf[s][3].w;
        }
        // wf from hoisted W regs + smem alphas
        {
            int oA = 2 * p + toA, oB = 2 * p + toB;
            wf[lt]      = wA0 * asm_[oA] + wA1 * asm_[8 + oA] + wA2 * asm_[16 + oA];
            wf[lt + 36] = wB0 * asm_[oB] + wB1 * asm_[8 + oB] + wB2 * asm_[16 + oB];
        }
        __syncthreads();

        // prefetch NEXT pair; latency overlaps FMA block
        if (p < TT / 2 - 1) {
            #pragma unroll
            for (int s = 0; s < 2; ++s) {
                const float* gx = xbase + (size_t)(t + 2 + s) * HW_ + lt * 8;
                pf[s][0] = ((const float4*)gx)[0]; pf[s][1] = ((const float4*)gx)[1];
                pf[s][2] = ((const float4*)(gx + 288))[0]; pf[s][3] = ((const float4*)(gx + 288))[1];
            }
        }

        float ak[2][2][8];
        #pragma unroll
        for (int i = 0; i < 2; ++i)
            #pragma unroll
            for (int r = 0; r < 2; ++r)
                #pragma unroll
                for (int wi = 0; wi < 8; ++wi) ak[i][r][wi] = 0.f;

        #pragma unroll
        for (int si = 0; si < 4; ++si) {
            int slot = (t - 2 + si) & 3;
            const float* sb = base + slot * SLICE;
            #pragma unroll
            for (int ri = 0; ri < 4; ++ri) {
                const float* rp = sb + (h0 + ri) * RS + w0;  // 4-aligned
                float4 f0 = ((const float4*)rp)[0];
                float4 f1 = ((const float4*)rp)[1];
                float4 f2 = ((const float4*)rp)[2];
                float row[12] = {f0.x,f0.y,f0.z,f0.w, f1.x,f1.y,f1.z,f1.w,
                                 f2.x,f2.y,f2.z,f2.w};
                #pragma unroll
                for (int to = 0; to < 2; ++to) {
                    int d = si - to;
                    if (d < 0 || d > 2) continue;       // compile-time after unroll
                    #pragma unroll
                    for (int r = 0; r < 2; ++r) {
                        int dh = ri - r;
                        if (dh < 0 || dh > 2) continue; // compile-time after unroll
                        float4 wq = *(const float4*)&wf[(to * 9 + d * 3 + dh) * 4];
                        float wv3[3] = {wq.x, wq.y, wq.z};
                        #pragma unroll
                        for (int dw = 0; dw < 3; ++dw) {
                            #pragma unroll
                            for (int wi = 0; wi < 8; ++wi)
                                ak[to][r][wi] = fmaf(wv3[dw], row[wi + dw], ak[to][r][wi]);
                        }
                    }
                }
            }
        }
        #pragma unroll
        for (int to = 0; to < 2; ++to)
            #pragma unroll
            for (int r = 0; r < 2; ++r) {
                size_t off = (size_t)(t + to) * HW_ + (h0 + r) * W_ + w0;
                ((float4*)(obase + off))[0] =
                    make_float4(ak[to][r][0], ak[to][r][1], ak[to][r][2], ak[to][r][3]);
                ((float4*)(obase + off))[1] =
                    make_float4(ak[to][r][4], ak[to][r][5], ak[to][r][6], ak[to][r][7]);
            }
    }
}

// ---------------------------------------------------------------------------
// Launch. inputs: 0=q 1=k 2=v 3=Wk 4=Wv 5=pre_w 6=pre_b 7=mix_w 8=mix_b
// ---------------------------------------------------------------------------
extern "C" void kernel_launch(void* const* d_in, const int* in_sizes, int n_in,
                              void* d_out, int out_size) {
    const float* q     = (const float*)d_in[0];
    const float* k     = (const float*)d_in[1];
    const float* v     = (const float*)d_in[2];
    const float* Wk    = (const float*)d_in[3];
    const float* Wv    = (const float*)d_in[4];
    const float* pre_w = (const float*)d_in[5];
    const float* pre_b = (const float*)d_in[6];
    const float* mix_w = (const float*)d_in[7];
    const float* mix_b = (const float*)d_in[8];
    float* out = (float*)d_out;

    pool_kernel<<<(B_ * C_ * T_) / 8, 256>>>((const float4*)q);
    {
        dim3 g(B_, 4);
        mix_kernel<<<g, 256>>>(pre_w, pre_b, mix_w, mix_b);
    }
    {
        dim3 g(T_ / TT, C_ / 2, B_ * 2);
        conv_kernel<<<g, 72>>>(k, v, Wk, Wv, out);
    }
}

// round 16
// speedup vs baseline: 1.1360x; 1.1360x over previous
#include <cuda_runtime.h>
#include <math.h>

#define B_ 4
#define C_ 128
#define T_ 32
#define H_ 24
#define W_ 24
#define M_ 3
#define HW_ (H_*W_)               // 576
#define NPER (B_*C_*T_*HW_)       // 9437184 elements per output tensor

// Scratch (device globals; no allocation allowed)
__device__ float g_qg[B_*T_*C_];     // [b][t][c]  pooled q
__device__ float g_alpha[B_*M_*T_];  // [b][m][t]  softmax mixture weights

// ---------------------------------------------------------------------------
// Kernel 1: spatial mean pool of q. One WARP per TWO (b,c,t) slices (t, t+1 of
// the same (b,c)) -> ~18 outstanding LDG.128 per lane for DRAM latency hiding.
// ---------------------------------------------------------------------------
__global__ __launch_bounds__(256) void pool_kernel(const float4* __restrict__ q4) {
    int w = threadIdx.x >> 5, lane = threadIdx.x & 31;
    int sidx = (blockIdx.x * 8 + w) * 2;           // slice pair
    const float4* p0 = q4 + (size_t)sidx * 144;
    const float4* p1 = p0 + 144;
    float4 a0 = p0[lane], b0 = p0[lane + 32], c0 = p0[lane + 64], d0 = p0[lane + 96];
    float4 a1 = p1[lane], b1 = p1[lane + 32], c1 = p1[lane + 64], d1 = p1[lane + 96];
    float s0 = a0.x+a0.y+a0.z+a0.w + b0.x+b0.y+b0.z+b0.w
             + c0.x+c0.y+c0.z+c0.w + d0.x+d0.y+d0.z+d0.w;
    float s1 = a1.x+a1.y+a1.z+a1.w + b1.x+b1.y+b1.z+b1.w
             + c1.x+c1.y+c1.z+c1.w + d1.x+d1.y+d1.z+d1.w;
    if (lane < 16) {
        float4 e0 = p0[lane + 128], e1 = p1[lane + 128];
        s0 += e0.x + e0.y + e0.z + e0.w;
        s1 += e1.x + e1.y + e1.z + e1.w;
    }
    #pragma unroll
    for (int o = 16; o; o >>= 1) {
        s0 += __shfl_down_sync(0xffffffffu, s0, o);
        s1 += __shfl_down_sync(0xffffffffu, s1, o);
    }
    if (lane == 0) {
        int t = sidx % T_, c = (sidx / T_) % C_, b = sidx / (T_ * C_);
        g_qg[(b * T_ + t) * C_ + c]     = s0 * (1.0f / HW_);
        g_qg[(b * T_ + t + 1) * C_ + c] = s1 * (1.0f / HW_);
    }
}

// ---------------------------------------------------------------------------
// Kernel 2 (measured ~5us): grid (B, 4). Each block owns 8 output timesteps,
// recomputes 2-timestep causal halo locally.
// ---------------------------------------------------------------------------
__global__ __launch_bounds__(256) void mix_kernel(const float* __restrict__ pre_w,
                                                  const float* __restrict__ pre_b,
                                                  const float* __restrict__ mix_w,
                                                  const float* __restrict__ mix_b) {
    int b = blockIdx.x, tg = blockIdx.y, tid = threadIdx.x;
    const int T0 = tg * 8;
    __shared__ float sq[10 * C_];
    __shared__ float sh[10 * C_];
    __shared__ float wsm[M_ * 3 * C_];
    __shared__ float lg[M_ * 8];

    for (int i = tid; i < 10 * (C_ / 4); i += 256) {
        int row = i / (C_ / 4), c4i = i % (C_ / 4);
        int tt = T0 - 2 + row;
        float4 val = make_float4(0.f, 0.f, 0.f, 0.f);
        if (tt >= 0) val = ((const float4*)(g_qg + (b * T_ + tt) * C_))[c4i];
        ((float4*)sq)[i] = val;
    }
    for (int i = tid; i < M_ * C_ * 3; i += 256) {
        int m = i / (C_ * 3), r = i % (C_ * 3);
        int cc = r / 3, j = r % 3;
        wsm[(m * 3 + j) * C_ + cc] = mix_w[i];
    }
    __syncthreads();

    int o = tid & 127, grp = tid >> 7;
    float acc[10];
    #pragma unroll
    for (int i = 0; i < 10; ++i) acc[i] = 0.f;

    const float4* wrow = (const float4*)(pre_w + o * C_) + grp * 16;
    #pragma unroll 4
    for (int c4 = 0; c4 < 16; ++c4) {
        float4 wv = wrow[c4];
        int cbase = grp * 64 + c4 * 4;
        #pragma unroll
        for (int i = 0; i < 10; ++i) {
            float4 sv = *(const float4*)&sq[i * C_ + cbase];
            acc[i] = fmaf(wv.x, sv.x,
                     fmaf(wv.y, sv.y,
                     fmaf(wv.z, sv.z,
                     fmaf(wv.w, sv.w, acc[i]))));
        }
    }
    __syncthreads();
    if (grp == 1) {
        #pragma unroll
        for (int i = 0; i < 10; ++i) sq[i * C_ + o] = acc[i];
    }
    __syncthreads();
    if (grp == 0) {
        float pb = pre_b[o];
        #pragma unroll
        for (int i = 0; i < 10; ++i) {
            float x = acc[i] + sq[i * C_ + o] + pb;
            sh[i * C_ + o] = 0.5f * x * (1.0f + erff(x * 0.70710678118654752440f));
        }
    }
    __syncthreads();

    if (tid < 24) {
        int m = tid / 8, tl = tid % 8;
        float a0 = mix_b[m], a1 = 0.f, a2 = 0.f, a3 = 0.f;
        #pragma unroll
        for (int j = 0; j < 3; ++j) {
            int tt = T0 + tl - 2 + j;
            if (tt >= 0) {
                const float* hp = sh + (tl + j) * C_;
                const float* wp = wsm + (m * 3 + j) * C_;
                #pragma unroll 4
                for (int c = 0; c < C_; c += 4) {
                    a0 = fmaf(wp[c],     hp[c],     a0);
                    a1 = fmaf(wp[c + 1], hp[c + 1], a1);
                    a2 = fmaf(wp[c + 2], hp[c + 2], a2);
                    a3 = fmaf(wp[c + 3], hp[c + 3], a3);
                }
            }
        }
        lg[m * 8 + tl] = (a0 + a1) + (a2 + a3);
    }
    __syncthreads();
    if (tid < 8) {
        int t = T0 + tid;
        float l0 = lg[tid], l1 = lg[8 + tid], l2 = lg[16 + tid];
        float mx = fmaxf(l0, fmaxf(l1, l2));
        float e0 = expf(l0 - mx), e1 = expf(l1 - mx), e2 = expf(l2 - mx);
        float inv = 1.f / (e0 + e1 + e2);
        g_alpha[(b * M_ + 0) * T_ + t] = e0 * inv;
        g_alpha[(b * M_ + 1) * T_ + t] = e1 * inv;
        g_alpha[(b * M_ + 2) * T_ + t] = e2 * inv;
    }
}

// ---------------------------------------------------------------------------
// Kernel 3: mixture depthwise causal 3D conv. ONE (tensor, channel) per block:
// smem = 4 slices (11.9KB) -> ~18 blocks/SM -> occupancy ~2x R14's 31.7%.
// Inner tiling identical to R14 (proven): 2 rows x 4 cols x 2 timesteps per
// thread, register prefetch double-buffer, hoisted W taps, staged alphas.
// ---------------------------------------------------------------------------
#define TT    8
#define RS    28       // padded row stride (floats)
#define SLICE (26*RS)  // 728 floats per padded slice

__global__ __launch_bounds__(72) void conv_kernel(
    const float* __restrict__ kin, const float* __restrict__ vin,
    const float* __restrict__ Wk,  const float* __restrict__ Wv,
    float* __restrict__ out) {
    __shared__ float sm[4 * SLICE + 72 + 32];  // 4 slices + wf + alphas
    float* wf   = sm + 4 * SLICE;              // 72 entries (one tensor)
    float* asm_ = wf + 72;                     // alphas [m][8]

    int t0 = blockIdx.x * TT;
    int c = blockIdx.y;
    int z = blockIdx.z;                        // b*2 + tsel
    int b = z >> 1, tsel = z & 1;
    int tid = threadIdx.x;
    int hi = tid / 6, seg = tid % 6;
    int h0 = hi * 2, w0 = seg * 4;
    int lrow = tid / 3, lcol = (tid % 3) * 8;

    size_t bc = (size_t)b * C_ + c;
    const float* xbase = (tsel ? vin : kin) + bc * T_ * HW_;
    float* obase = out + (size_t)tsel * NPER + bc * T_ * HW_;
    const float* Wc = (tsel ? Wv : Wk) + c * 27;

    // hoist W taps for this thread's wf slot (idx = tid; 72 = 2to*9qd*4dw)
    float wA0 = 0.f, wA1 = 0.f, wA2 = 0.f;
    int toA;
    {
        int dw = tid & 3, g = tid >> 2;        // g = to*9 + qd
        toA = g / 9;
        int qd = g % 9;
        int j = (qd / 3) * 9 + (qd % 3) * 3 + dw;
        if (dw < 3) {
            wA0 = Wc[j]; wA1 = Wc[C_ * 27 + j]; wA2 = Wc[2 * C_ * 27 + j];
        }
    }

    // zero all slices (borders + temporal zero padding)
    for (int i = tid; i < (4 * SLICE) / 4; i += 72)
        ((float4*)sm)[i] = make_float4(0.f, 0.f, 0.f, 0.f);
    // stage alphas for this block's 8 timesteps
    if (tid < 24) {
        int m = tid / 8, tl = tid % 8;
        asm_[m * 8 + tl] = g_alpha[(b * M_ + m) * T_ + t0 + tl];
    }
    __syncthreads();   // zeros + alphas visible

    // halo slices t0-2, t0-1
    #pragma unroll
    for (int s = 0; s < 2; ++s) {
        int tt = t0 - 2 + s;
        if (tt >= 0) {
            int slot = tt & 3;
            const float* gx = xbase + (size_t)tt * HW_ + tid * 8;
            float4 x0 = ((const float4*)gx)[0], x1 = ((const float4*)gx)[1];
            float* d = sm + slot * SLICE + (lrow + 1) * RS + lcol + 1;
            d[0]=x0.x; d[1]=x0.y; d[2]=x0.z; d[3]=x0.w;
            d[4]=x1.x; d[5]=x1.y; d[6]=x1.z; d[7]=x1.w;
        }
    }

    // prefetch first body pair (t0, t0+1)
    float4 pf[2][2];
    #pragma unroll
    for (int s = 0; s < 2; ++s) {
        const float* gx = xbase + (size_t)(t0 + s) * HW_ + tid * 8;
        pf[s][0] = ((const float4*)gx)[0];
        pf[s][1] = ((const float4*)gx)[1];
    }

    #pragma unroll 1
    for (int p = 0; p < TT / 2; ++p) {
        int t = t0 + 2 * p;
        __syncthreads();   // previous iter's reads done before slot overwrite
        #pragma unroll
        for (int s = 0; s < 2; ++s) {
            int slot = (t + s) & 3;
            float* d = sm + slot * SLICE + (lrow + 1) * RS + lcol + 1;
            d[0]=pf[s][0].x; d[1]=pf[s][0].y; d[2]=pf[s][0].z; d[3]=pf[s][0].w;
            d[4]=pf[s][1].x; d[5]=pf[s][1].y; d[6]=pf[s][1].z; d[7]=pf[s][1].w;
        }
        // wf from hoisted W regs + smem alphas
        {
            int oA = 2 * p + toA;
            wf[tid] = wA0 * asm_[oA] + wA1 * asm_[8 + oA] + wA2 * asm_[16 + oA];
        }
        __syncthreads();

        // prefetch NEXT pair; latency overlaps FMA block
        if (p < TT / 2 - 1) {
            #pragma unroll
            for (int s = 0; s < 2; ++s) {
                const float* gx = xbase + (size_t)(t + 2 + s) * HW_ + tid * 8;
                pf[s][0] = ((const float4*)gx)[0];
                pf[s][1] = ((const float4*)gx)[1];
            }
        }

        float ak[2][2][4];
        #pragma unroll
        for (int i = 0; i < 2; ++i)
            #pragma unroll
            for (int r = 0; r < 2; ++r)
                #pragma unroll
                for (int wi = 0; wi < 4; ++wi) ak[i][r][wi] = 0.f;

        #pragma unroll
        for (int si = 0; si < 4; ++si) {
            int slot = (t - 2 + si) & 3;
            const float* sb = sm + slot * SLICE;
            #pragma unroll
            for (int ri = 0; ri < 4; ++ri) {
                const float* rp = sb + (h0 + ri) * RS + w0;   // aligned float4
                float4 f0 = ((const float4*)rp)[0], f1 = ((const float4*)rp)[1];
                float row[8] = {f0.x,f0.y,f0.z,f0.w,f1.x,f1.y,f1.z,f1.w};
                #pragma unroll
                for (int to = 0; to < 2; ++to) {
                    int d = si - to;
                    if (d < 0 || d > 2) continue;       // compile-time after unroll
                    #pragma unroll
                    for (int r = 0; r < 2; ++r) {
                        int dh = ri - r;
                        if (dh < 0 || dh > 2) continue; // compile-time after unroll
                        float4 wq = *(const float4*)&wf[(to * 9 + d * 3 + dh) * 4];
                        float wv3[3] = {wq.x, wq.y, wq.z};
                        #pragma unroll
                        for (int dw = 0; dw < 3; ++dw) {
                            #pragma unroll
                            for (int wi = 0; wi < 4; ++wi)
                                ak[to][r][wi] = fmaf(wv3[dw], row[wi + dw], ak[to][r][wi]);
                        }
                    }
                }
            }
        }
        #pragma unroll
        for (int to = 0; to < 2; ++to)
            #pragma unroll
            for (int r = 0; r < 2; ++r) {
                size_t off = (size_t)(t + to) * HW_ + (h0 + r) * W_ + w0;
                ((float4*)(obase + off))[0] =
                    make_float4(ak[to][r][0], ak[to][r][1], ak[to][r][2], ak[to][r][3]);
            }
    }
}

// ---------------------------------------------------------------------------
// Launch. inputs: 0=q 1=k 2=v 3=Wk 4=Wv 5=pre_w 6=pre_b 7=mix_w 8=mix_b
// ---------------------------------------------------------------------------
extern "C" void kernel_launch(void* const* d_in, const int* in_sizes, int n_in,
                              void* d_out, int out_size) {
    const float* q     = (const float*)d_in[0];
    const float* k     = (const float*)d_in[1];
    const float* v     = (const float*)d_in[2];
    const float* Wk    = (const float*)d_in[3];
    const float* Wv    = (const float*)d_in[4];
    const float* pre_w = (const float*)d_in[5];
    const float* pre_b = (const float*)d_in[6];
    const float* mix_w = (const float*)d_in[7];
    const float* mix_b = (const float*)d_in[8];
    float* out = (float*)d_out;

    pool_kernel<<<(B_ * C_ * T_) / 16, 256>>>((const float4*)q);
    {
        dim3 g(B_, 4);
        mix_kernel<<<g, 256>>>(pre_w, pre_b, mix_w, mix_b);
    }
    {
        dim3 g(T_ / TT, C_, B_ * 2);
        conv_kernel<<<g, 72>>>(k, v, Wk, Wv, out);
    }
}

// round 17
// speedup vs baseline: 1.1700x; 1.0300x over previous
#include <cuda_runtime.h>
#include <math.h>

#define B_ 4
#define C_ 128
#define T_ 32
#define H_ 24
#define W_ 24
#define M_ 3
#define HW_ (H_*W_)               // 576
#define NPER (B_*C_*T_*HW_)       // 9437184 elements per output tensor

// Scratch (device globals; no allocation allowed)
__device__ float g_qg[B_*T_*C_];     // [b][t][c]  pooled q
__device__ float g_alpha[B_*M_*T_];  // [b][m][t]  softmax mixture weights

// ---------------------------------------------------------------------------
// Kernel 1: spatial mean pool of q. One WARP per TWO (b,c,t) slices.
// ---------------------------------------------------------------------------
__global__ __launch_bounds__(256) void pool_kernel(const float4* __restrict__ q4) {
    int w = threadIdx.x >> 5, lane = threadIdx.x & 31;
    int sidx = (blockIdx.x * 8 + w) * 2;           // slice pair
    const float4* p0 = q4 + (size_t)sidx * 144;
    const float4* p1 = p0 + 144;
    float4 a0 = p0[lane], b0 = p0[lane + 32], c0 = p0[lane + 64], d0 = p0[lane + 96];
    float4 a1 = p1[lane], b1 = p1[lane + 32], c1 = p1[lane + 64], d1 = p1[lane + 96];
    float s0 = a0.x+a0.y+a0.z+a0.w + b0.x+b0.y+b0.z+b0.w
             + c0.x+c0.y+c0.z+c0.w + d0.x+d0.y+d0.z+d0.w;
    float s1 = a1.x+a1.y+a1.z+a1.w + b1.x+b1.y+b1.z+b1.w
             + c1.x+c1.y+c1.z+c1.w + d1.x+d1.y+d1.z+d1.w;
    if (lane < 16) {
        float4 e0 = p0[lane + 128], e1 = p1[lane + 128];
        s0 += e0.x + e0.y + e0.z + e0.w;
        s1 += e1.x + e1.y + e1.z + e1.w;
    }
    #pragma unroll
    for (int o = 16; o; o >>= 1) {
        s0 += __shfl_down_sync(0xffffffffu, s0, o);
        s1 += __shfl_down_sync(0xffffffffu, s1, o);
    }
    if (lane == 0) {
        int t = sidx % T_, c = (sidx / T_) % C_, b = sidx / (T_ * C_);
        g_qg[(b * T_ + t) * C_ + c]     = s0 * (1.0f / HW_);
        g_qg[(b * T_ + t + 1) * C_ + c] = s1 * (1.0f / HW_);
    }
}

// ---------------------------------------------------------------------------
// Kernel 2: grid (B, 8). Each block owns 4 output timesteps + 2-row causal
// halo (6 rows total). 2x parallelism vs (B,4) version.
// ---------------------------------------------------------------------------
__global__ __launch_bounds__(256) void mix_kernel(const float* __restrict__ pre_w,
                                                  const float* __restrict__ pre_b,
                                                  const float* __restrict__ mix_w,
                                                  const float* __restrict__ mix_b) {
    int b = blockIdx.x, tg = blockIdx.y, tid = threadIdx.x;
    const int T0 = tg * 4;
    __shared__ float sq[6 * C_];
    __shared__ float sh[6 * C_];
    __shared__ float wsm[M_ * 3 * C_];
    __shared__ float lg[M_ * 4];

    for (int i = tid; i < 6 * (C_ / 4); i += 256) {
        int row = i / (C_ / 4), c4i = i % (C_ / 4);
        int tt = T0 - 2 + row;
        float4 val = make_float4(0.f, 0.f, 0.f, 0.f);
        if (tt >= 0) val = ((const float4*)(g_qg + (b * T_ + tt) * C_))[c4i];
        ((float4*)sq)[i] = val;
    }
    for (int i = tid; i < M_ * C_ * 3; i += 256) {
        int m = i / (C_ * 3), r = i % (C_ * 3);
        int cc = r / 3, j = r % 3;
        wsm[(m * 3 + j) * C_ + cc] = mix_w[i];
    }
    __syncthreads();

    int o = tid & 127, grp = tid >> 7;
    float acc[6];
    #pragma unroll
    for (int i = 0; i < 6; ++i) acc[i] = 0.f;

    const float4* wrow = (const float4*)(pre_w + o * C_) + grp * 16;
    #pragma unroll 4
    for (int c4 = 0; c4 < 16; ++c4) {
        float4 wv = wrow[c4];
        int cbase = grp * 64 + c4 * 4;
        #pragma unroll
        for (int i = 0; i < 6; ++i) {
            float4 sv = *(const float4*)&sq[i * C_ + cbase];
            acc[i] = fmaf(wv.x, sv.x,
                     fmaf(wv.y, sv.y,
                     fmaf(wv.z, sv.z,
                     fmaf(wv.w, sv.w, acc[i]))));
        }
    }
    __syncthreads();
    if (grp == 1) {
        #pragma unroll
        for (int i = 0; i < 6; ++i) sq[i * C_ + o] = acc[i];
    }
    __syncthreads();
    if (grp == 0) {
        float pb = pre_b[o];
        #pragma unroll
        for (int i = 0; i < 6; ++i) {
            float x = acc[i] + sq[i * C_ + o] + pb;
            sh[i * C_ + o] = 0.5f * x * (1.0f + erff(x * 0.70710678118654752440f));
        }
    }
    __syncthreads();

    if (tid < 12) {
        int m = tid / 4, tl = tid % 4;
        float a0 = mix_b[m], a1 = 0.f, a2 = 0.f, a3 = 0.f;
        #pragma unroll
        for (int j = 0; j < 3; ++j) {
            int tt = T0 + tl - 2 + j;
            if (tt >= 0) {
                const float* hp = sh + (tl + j) * C_;
                const float* wp = wsm + (m * 3 + j) * C_;
                #pragma unroll 4
                for (int c = 0; c < C_; c += 4) {
                    a0 = fmaf(wp[c],     hp[c],     a0);
                    a1 = fmaf(wp[c + 1], hp[c + 1], a1);
                    a2 = fmaf(wp[c + 2], hp[c + 2], a2);
                    a3 = fmaf(wp[c + 3], hp[c + 3], a3);
                }
            }
        }
        lg[m * 4 + tl] = (a0 + a1) + (a2 + a3);
    }
    __syncthreads();
    if (tid < 4) {
        int t = T0 + tid;
        float l0 = lg[tid], l1 = lg[4 + tid], l2 = lg[8 + tid];
        float mx = fmaxf(l0, fmaxf(l1, l2));
        float e0 = expf(l0 - mx), e1 = expf(l1 - mx), e2 = expf(l2 - mx);
        float inv = 1.f / (e0 + e1 + e2);
        g_alpha[(b * M_ + 0) * T_ + t] = e0 * inv;
        g_alpha[(b * M_ + 1) * T_ + t] = e1 * inv;
        g_alpha[(b * M_ + 2) * T_ + t] = e2 * inv;
    }
}

// ---------------------------------------------------------------------------
// Kernel 3: mixture depthwise causal 3D conv. ONE (tensor, channel) per block,
// TT=16 timesteps per block (halo overhead 12.5% vs 25%). Inner tiling as R16:
// 2 rows x 4 cols x 2 timesteps per thread, register prefetch double-buffer,
// hoisted per-thread W taps, staged alphas.
// ---------------------------------------------------------------------------
#define TT    16
#define RS    28       // padded row stride (floats)
#define SLICE (26*RS)  // 728 floats per padded slice

__global__ __launch_bounds__(72) void conv_kernel(
    const float* __restrict__ kin, const float* __restrict__ vin,
    const float* __restrict__ Wk,  const float* __restrict__ Wv,
    float* __restrict__ out) {
    __shared__ float sm[4 * SLICE + 72 + 48];  // 4 slices + wf + alphas
    float* wf   = sm + 4 * SLICE;              // 72 entries (one tensor)
    float* asm_ = wf + 72;                     // alphas [m][16]

    int t0 = blockIdx.x * TT;
    int c = blockIdx.y;
    int z = blockIdx.z;                        // b*2 + tsel
    int b = z >> 1, tsel = z & 1;
    int tid = threadIdx.x;
    int hi = tid / 6, seg = tid % 6;
    int h0 = hi * 2, w0 = seg * 4;
    int lrow = tid / 3, lcol = (tid % 3) * 8;

    size_t bc = (size_t)b * C_ + c;
    const float* xbase = (tsel ? vin : kin) + bc * T_ * HW_;
    float* obase = out + (size_t)tsel * NPER + bc * T_ * HW_;
    const float* Wc = (tsel ? Wv : Wk) + c * 27;

    // stage alphas for this block's 16 timesteps (early LDG, overlaps zeroing)
    float aval = 0.f;
    if (tid < 48) {
        int m = tid / 16, tl = tid % 16;
        aval = g_alpha[(b * M_ + m) * T_ + t0 + tl];
    }

    // hoist W taps for this thread's wf slot (idx = tid; 72 = 2to*9qd*4dw)
    float wA0 = 0.f, wA1 = 0.f, wA2 = 0.f;
    int toA;
    {
        int dw = tid & 3, g = tid >> 2;        // g = to*9 + qd
        toA = g / 9;
        int qd = g % 9;
        int j = (qd / 3) * 9 + (qd % 3) * 3 + dw;
        if (dw < 3) {
            wA0 = Wc[j]; wA1 = Wc[C_ * 27 + j]; wA2 = Wc[2 * C_ * 27 + j];
        }
    }

    // zero all slices (borders + temporal zero padding)
    for (int i = tid; i < (4 * SLICE) / 4; i += 72)
        ((float4*)sm)[i] = make_float4(0.f, 0.f, 0.f, 0.f);
    if (tid < 48) asm_[tid] = aval;           // [m][16] layout: m=tid/16
    __syncthreads();   // zeros + alphas visible

    // halo slices t0-2, t0-1
    #pragma unroll
    for (int s = 0; s < 2; ++s) {
        int tt = t0 - 2 + s;
        if (tt >= 0) {
            int slot = tt & 3;
            const float* gx = xbase + (size_t)tt * HW_ + tid * 8;
            float4 x0 = ((const float4*)gx)[0], x1 = ((const float4*)gx)[1];
            float* d = sm + slot * SLICE + (lrow + 1) * RS + lcol + 1;
            d[0]=x0.x; d[1]=x0.y; d[2]=x0.z; d[3]=x0.w;
            d[4]=x1.x; d[5]=x1.y; d[6]=x1.z; d[7]=x1.w;
        }
    }

    // prefetch first body pair (t0, t0+1)
    float4 pf[2][2];
    #pragma unroll
    for (int s = 0; s < 2; ++s) {
        const float* gx = xbase + (size_t)(t0 + s) * HW_ + tid * 8;
        pf[s][0] = ((const float4*)gx)[0];
        pf[s][1] = ((const float4*)gx)[1];
    }

    #pragma unroll 1
    for (int p = 0; p < TT / 2; ++p) {
        int t = t0 + 2 * p;
        __syncthreads();   // previous iter's reads done before slot overwrite
        #pragma unroll
        for (int s = 0; s < 2; ++s) {
            int slot = (t + s) & 3;
            float* d = sm + slot * SLICE + (lrow + 1) * RS + lcol + 1;
            d[0]=pf[s][0].x; d[1]=pf[s][0].y; d[2]=pf[s][0].z; d[3]=pf[s][0].w;
            d[4]=pf[s][1].x; d[5]=pf[s][1].y; d[6]=pf[s][1].z; d[7]=pf[s][1].w;
        }
        // wf from hoisted W regs + smem alphas
        {
            int oA = 2 * p + toA;
            wf[tid] = wA0 * asm_[oA] + wA1 * asm_[16 + oA] + wA2 * asm_[32 + oA];
        }
        __syncthreads();

        // prefetch NEXT pair; latency overlaps FMA block
        if (p < TT / 2 - 1) {
            #pragma unroll
            for (int s = 0; s < 2; ++s) {
                const float* gx = xbase + (size_t)(t + 2 + s) * HW_ + tid * 8;
                pf[s][0] = ((const float4*)gx)[0];
                pf[s][1] = ((const float4*)gx)[1];
            }
        }

        float ak[2][2][4];
        #pragma unroll
        for (int i = 0; i < 2; ++i)
            #pragma unroll
            for (int r = 0; r < 2; ++r)
                #pragma unroll
                for (int wi = 0; wi < 4; ++wi) ak[i][r][wi] = 0.f;

        #pragma unroll
        for (int si = 0; si < 4; ++si) {
            int slot = (t - 2 + si) & 3;
            const float* sb = sm + slot * SLICE;
            #pragma unroll
            for (int ri = 0; ri < 4; ++ri) {
                const float* rp = sb + (h0 + ri) * RS + w0;   // aligned float4
                float4 f0 = ((const float4*)rp)[0], f1 = ((const float4*)rp)[1];
                float row[8] = {f0.x,f0.y,f0.z,f0.w,f1.x,f1.y,f1.z,f1.w};
                #pragma unroll
                for (int to = 0; to < 2; ++to) {
                    int d = si - to;
                    if (d < 0 || d > 2) continue;       // compile-time after unroll
                    #pragma unroll
                    for (int r = 0; r < 2; ++r) {
                        int dh = ri - r;
                        if (dh < 0 || dh > 2) continue; // compile-time after unroll
                        float4 wq = *(const float4*)&wf[(to * 9 + d * 3 + dh) * 4];
                        float wv3[3] = {wq.x, wq.y, wq.z};
                        #pragma unroll
                        for (int dw = 0; dw < 3; ++dw) {
                            #pragma unroll
                            for (int wi = 0; wi < 4; ++wi)
                                ak[to][r][wi] = fmaf(wv3[dw], row[wi + dw], ak[to][r][wi]);
                        }
                    }
                }
            }
        }
        #pragma unroll
        for (int to = 0; to < 2; ++to)
            #pragma unroll
            for (int r = 0; r < 2; ++r) {
                size_t off = (size_t)(t + to) * HW_ + (h0 + r) * W_ + w0;
                ((float4*)(obase + off))[0] =
                    make_float4(ak[to][r][0], ak[to][r][1], ak[to][r][2], ak[to][r][3]);
            }
    }
}

// ---------------------------------------------------------------------------
// Launch. inputs: 0=q 1=k 2=v 3=Wk 4=Wv 5=pre_w 6=pre_b 7=mix_w 8=mix_b
// ---------------------------------------------------------------------------
extern "C" void kernel_launch(void* const* d_in, const int* in_sizes, int n_in,
                              void* d_out, int out_size) {
    const float* q     = (const float*)d_in[0];
    const float* k     = (const float*)d_in[1];
    const float* v     = (const float*)d_in[2];
    const float* Wk    = (const float*)d_in[3];
    const float* Wv    = (const float*)d_in[4];
    const float* pre_w = (const float*)d_in[5];
    const float* pre_b = (const float*)d_in[6];
    const float* mix_w = (const float*)d_in[7];
    const float* mix_b = (const float*)d_in[8];
    float* out = (float*)d_out;

    pool_kernel<<<(B_ * C_ * T_) / 16, 256>>>((const float4*)q);
    {
        dim3 g(B_, 8);
        mix_kernel<<<g, 256>>>(pre_w, pre_b, mix_w, mix_b);
    }
    {
        dim3 g(T_ / TT, C_, B_ * 2);
        conv_kernel<<<g, 72>>>(k, v, Wk, Wv, out);
    }
}